// round 3
// baseline (speedup 1.0000x reference)
#include <cuda_runtime.h>
#include <cstdint>

// Problem constants (match reference)
#define NUM_CENTERS 1000
#define CAPACITY    512
#define FEAT_DIM    256
#define BATCH       65536

#define VEC_PER_ROW     (FEAT_DIM / 4)       // 64 float4 per row (1 KB)
#define SAMPLES_PER_BLK 256
#define THREADS         256
#define ROUNDS          8                     // copy rounds per block
#define VEC_PER_ROUND   8                     // independent LDG.128 per thread per round
// total per block: 256 rows * 64 f4 = 16384 f4 = 8 rounds * 256 thr * 8

__global__ __launch_bounds__(THREADS)
void noise_bank_gather(const int* __restrict__ tgt,
                       const int* __restrict__ ridx,
                       const int* __restrict__ counts,
                       const float4* __restrict__ bank,
                       const float4* __restrict__ fallback,
                       float4* __restrict__ out)
{
    __shared__ const float4* srcs[SAMPLES_PER_BLK];

    const int tid  = threadIdx.x;
    const int base = blockIdx.x * SAMPLES_PER_BLK;

    // Phase A: every thread resolves exactly one sample's source pointer.
    // 256 independent 3-load chains in flight; exposed once per block.
    {
        const int sample = base + tid;
        const int c   = __ldg(&tgt[sample]);
        const int cnt = __ldg(&counts[c]);
        const float4* p;
        if (cnt > 0) {
            const int idx = __ldg(&ridx[sample]) % cnt;
            p = bank + ((int64_t)c * CAPACITY + idx) * VEC_PER_ROW;
        } else {
            p = fallback + (int64_t)sample * VEC_PER_ROW;
        }
        srcs[tid] = p;
    }
    __syncthreads();

    // Phase B: copy 256 rows (256 KB), 8 rounds, no barriers in between.
    // Round r covers positions [r*2048, (r+1)*2048): 32 rows. Each warp's
    // 32 lanes read a contiguous 512B slice of one row -> full coalescing.
    float4* const out_base = out + (int64_t)base * VEC_PER_ROW;

    #pragma unroll
    for (int r = 0; r < ROUNDS; ++r) {
        float4 v[VEC_PER_ROUND];
        #pragma unroll
        for (int k = 0; k < VEC_PER_ROUND; ++k) {
            const int pos  = r * (THREADS * VEC_PER_ROUND) + k * THREADS + tid;
            const int s    = pos >> 6;                  // row within block tile
            const int lane = pos & (VEC_PER_ROW - 1);   // float4 within row
            v[k] = __ldg(&srcs[s][lane]);
        }
        #pragma unroll
        for (int k = 0; k < VEC_PER_ROUND; ++k) {
            const int pos = r * (THREADS * VEC_PER_ROUND) + k * THREADS + tid;
            out_base[pos] = v[k];
        }
    }
}

extern "C" void kernel_launch(void* const* d_in, const int* in_sizes, int n_in,
                              void* d_out, int out_size)
{
    const int*    tgt      = (const int*)   d_in[0];  // target_center_ids [B]
    const int*    ridx     = (const int*)   d_in[1];  // rand_idx          [B]
    const int*    counts   = (const int*)   d_in[2];  // counts            [NUM_CENTERS]
    const float4* bank     = (const float4*)d_in[3];  // bank [NC, CAP, D]
    const float4* fallback = (const float4*)d_in[4];  // fallback_noise [B, D]
    float4*       out      = (float4*)      d_out;    // [B, D] fp32

    const int grid = BATCH / SAMPLES_PER_BLK;  // 256
    noise_bank_gather<<<grid, THREADS>>>(tgt, ridx, counts, bank, fallback, out);
}

// round 4
// speedup vs baseline: 1.4848x; 1.4848x over previous
#include <cuda_runtime.h>
#include <cstdint>

// Problem constants (match reference)
#define NUM_CENTERS 1000
#define CAPACITY    512
#define FEAT_DIM    256
#define BATCH       65536

#define VEC_PER_ROW     (FEAT_DIM / 4)       // 64 float4 per row (1 KB)
#define SAMPLES_PER_BLK 32
#define THREADS         256
#define TOTAL_VEC       (SAMPLES_PER_BLK * VEC_PER_ROW)   // 2048 float4
#define VEC_PER_THREAD  (TOTAL_VEC / THREADS)             // 8

__global__ __launch_bounds__(THREADS)
void noise_bank_gather(const int* __restrict__ tgt,
                       const int* __restrict__ ridx,
                       const int* __restrict__ counts,
                       const float4* __restrict__ bank,
                       const float4* __restrict__ fallback,
                       float4* __restrict__ out)
{
    __shared__ const float4* srcs[SAMPLES_PER_BLK];

    const int tid  = threadIdx.x;
    const int base = blockIdx.x * SAMPLES_PER_BLK;

    // Phase A: 32 threads resolve 32 independent source pointers.
    if (tid < SAMPLES_PER_BLK) {
        const int sample = base + tid;
        const int c   = __ldg(&tgt[sample]);
        const int cnt = __ldg(&counts[c]);
        const float4* p;
        if (cnt > 0) {
            const int idx = __ldg(&ridx[sample]) % cnt;
            p = bank + ((int64_t)c * CAPACITY + idx) * VEC_PER_ROW;
        } else {
            p = fallback + (int64_t)sample * VEC_PER_ROW;
        }
        srcs[tid] = p;
    }
    __syncthreads();

    // Phase B: copy 32 rows (32 KB). Each thread: 8 independent LDG.128.
    // Loads: default caching (want the gather set resident in L2 across
    // graph replays). Stores: streaming / evict-first (__stcs) so the
    // write-once output does NOT thrash L2 and evict the gather set.
    float4* const out_base = out + (int64_t)base * VEC_PER_ROW;

    float4 v[VEC_PER_THREAD];
    #pragma unroll
    for (int k = 0; k < VEC_PER_THREAD; ++k) {
        const int pos  = k * THREADS + tid;         // 0..2047
        const int s    = pos >> 6;                  // sample within block
        const int lane = pos & (VEC_PER_ROW - 1);   // float4 within row
        v[k] = __ldg(&srcs[s][lane]);
    }
    #pragma unroll
    for (int k = 0; k < VEC_PER_THREAD; ++k) {
        const int pos = k * THREADS + tid;
        __stcs(&out_base[pos], v[k]);
    }
}

extern "C" void kernel_launch(void* const* d_in, const int* in_sizes, int n_in,
                              void* d_out, int out_size)
{
    const int*    tgt      = (const int*)   d_in[0];  // target_center_ids [B]
    const int*    ridx     = (const int*)   d_in[1];  // rand_idx          [B]
    const int*    counts   = (const int*)   d_in[2];  // counts            [NUM_CENTERS]
    const float4* bank     = (const float4*)d_in[3];  // bank [NC, CAP, D]
    const float4* fallback = (const float4*)d_in[4];  // fallback_noise [B, D]
    float4*       out      = (float4*)      d_out;    // [B, D] fp32

    const int grid = BATCH / SAMPLES_PER_BLK;  // 2048
    noise_bank_gather<<<grid, THREADS>>>(tgt, ridx, counts, bank, fallback, out);
}